// round 3
// baseline (speedup 1.0000x reference)
#include <cuda_runtime.h>
#include <cuda_bf16.h>
#include <cstdint>

// MHC fused, persistent + cp.async smem ring (3 buffers, prefetch depth 2).
// Grid = #SMs, 1 CTA/SM, 512 threads. Each thread's smem slots are private
// (it copies and reads only its own 8 float4 per row), so the only barrier
// per row is the RMS block-reduce (parity slots).

#define NS        4
#define CDIM      4096
#define C4        (CDIM / 4)
#define THREADS   512
#define EPSF      1e-6f
#define SINKITERS 3
#define NBUF      3
#define STREAM_BYTES (CDIM * 4)          // 16384
#define ROW_BYTES    (NS * STREAM_BYTES) // 65536
#define SMEM_BYTES   (NBUF * ROW_BYTES)  // 196608

__device__ __forceinline__ void cp16(uint32_t saddr, const void* gaddr) {
    asm volatile("cp.async.cg.shared.global [%0], [%1], 16;\n"
                 :: "r"(saddr), "l"(gaddr) : "memory");
}
__device__ __forceinline__ void cp_commit() {
    asm volatile("cp.async.commit_group;\n" ::: "memory");
}
__device__ __forceinline__ void cp_wait2() {
    asm volatile("cp.async.wait_group 2;\n" ::: "memory");
}

__global__ __launch_bounds__(THREADS, 1)
void mhc_cpasync_kernel(const float* __restrict__ x,
                        const float* __restrict__ w,
                        const float* __restrict__ Hpre,
                        const float* __restrict__ Hpost,
                        const float* __restrict__ Hres,
                        float* __restrict__ out, int B)
{
    extern __shared__ unsigned char sm[];
    __shared__ float wsum[2][THREADS / 32];

    const int tid = threadIdx.x, lane = tid & 31, wid = tid >> 5;
    const int stride = gridDim.x;

    uint32_t smbase;
    asm("{ .reg .u64 t; cvta.to.shared.u64 t, %1; cvt.u32.u64 %0, t; }"
        : "=r"(smbase) : "l"(sm));

    // ---- Tiny params (redundant per thread, registers) ----
    float hpre[NS], hpost[NS];
    #pragma unroll
    for (int i = 0; i < NS; i++) {
        hpre[i]  = 1.0f / (1.0f + expf(-Hpre[i]));
        hpost[i] = 2.0f / (1.0f + expf(-Hpost[i]));
    }
    float P[NS][NS];
    #pragma unroll
    for (int i = 0; i < NS; i++)
        #pragma unroll
        for (int j = 0; j < NS; j++)
            P[i][j] = expf(Hres[i * NS + j]);
    #pragma unroll
    for (int it = 0; it < SINKITERS; it++) {
        #pragma unroll
        for (int i = 0; i < NS; i++) {
            float ri = 1.0f / (P[i][0] + P[i][1] + P[i][2] + P[i][3] + EPSF);
            #pragma unroll
            for (int j = 0; j < NS; j++) P[i][j] *= ri;
        }
        #pragma unroll
        for (int j = 0; j < NS; j++) {
            float ci = 1.0f / (P[0][j] + P[1][j] + P[2][j] + P[3][j] + EPSF);
            #pragma unroll
            for (int i = 0; i < NS; i++) P[i][j] *= ci;
        }
    }

    // rmsnorm weight: held in registers for the whole kernel
    const float4 wv0 = reinterpret_cast<const float4*>(w)[tid];
    const float4 wv1 = reinterpret_cast<const float4*>(w)[tid + THREADS];
    const float wa[8] = {wv0.x, wv0.y, wv0.z, wv0.w,
                         wv1.x, wv1.y, wv1.z, wv1.w};

    const char* __restrict__ xb = reinterpret_cast<const char*>(x);

    // ---- Prologue: prefetch rows r0, r0+stride ----
    const int r0 = blockIdx.x;
    {
        if (r0 < B) {
            const char* g = xb + (size_t)r0 * ROW_BYTES;
            uint32_t sb = smbase;  // buf 0
            #pragma unroll
            for (int n = 0; n < NS; n++) {
                cp16(sb + n * STREAM_BYTES + tid * 16,
                     g  + n * STREAM_BYTES + tid * 16);
                cp16(sb + n * STREAM_BYTES + (tid + THREADS) * 16,
                     g  + n * STREAM_BYTES + (tid + THREADS) * 16);
            }
        }
        cp_commit();
        if (r0 + stride < B) {
            const char* g = xb + (size_t)(r0 + stride) * ROW_BYTES;
            uint32_t sb = smbase + ROW_BYTES;  // buf 1
            #pragma unroll
            for (int n = 0; n < NS; n++) {
                cp16(sb + n * STREAM_BYTES + tid * 16,
                     g  + n * STREAM_BYTES + tid * 16);
                cp16(sb + n * STREAM_BYTES + (tid + THREADS) * 16,
                     g  + n * STREAM_BYTES + (tid + THREADS) * 16);
            }
        }
        cp_commit();
    }

    int k = 0;
    for (int r = r0; r < B; r += stride, k++) {
        // ---- Prefetch row r + 2*stride into buf (k+2)%3 ----
        const int rp = r + 2 * stride;
        if (rp < B) {
            const char* g = xb + (size_t)rp * ROW_BYTES;
            uint32_t sb = smbase + ((k + 2) % NBUF) * ROW_BYTES;
            #pragma unroll
            for (int n = 0; n < NS; n++) {
                cp16(sb + n * STREAM_BYTES + tid * 16,
                     g  + n * STREAM_BYTES + tid * 16);
                cp16(sb + n * STREAM_BYTES + (tid + THREADS) * 16,
                     g  + n * STREAM_BYTES + (tid + THREADS) * 16);
            }
        }
        cp_commit();
        cp_wait2();   // group for row r retired (<=2 groups still pending)

        // ---- Pull this thread's private slots smem -> registers ----
        const float4* __restrict__ buf =
            reinterpret_cast<const float4*>(sm + (k % NBUF) * ROW_BYTES);
        float va[NS][8];
        #pragma unroll
        for (int n = 0; n < NS; n++) {
            float4 a = buf[n * C4 + tid];
            float4 b = buf[n * C4 + tid + THREADS];
            va[n][0] = a.x; va[n][1] = a.y; va[n][2] = a.z; va[n][3] = a.w;
            va[n][4] = b.x; va[n][5] = b.y; va[n][6] = b.z; va[n][7] = b.w;
        }

        // ---- agg (sigmoid-gated sum), bf16 round-trip, sum of squares ----
        float agg[8];
        float ss = 0.0f;
        #pragma unroll
        for (int e = 0; e < 8; e++) {
            float a = hpre[0] * va[0][e] + hpre[1] * va[1][e]
                    + hpre[2] * va[2][e] + hpre[3] * va[3][e];
            a = __bfloat162float(__float2bfloat16_rn(a));
            agg[e] = a;
            ss += a * a;
        }

        // ---- Block reduce (single barrier, parity slots) ----
        #pragma unroll
        for (int o = 16; o > 0; o >>= 1)
            ss += __shfl_xor_sync(0xffffffffu, ss, o);
        float* ws = wsum[k & 1];
        if (lane == 0) ws[wid] = ss;
        __syncthreads();
        float tot = 0.0f;
        #pragma unroll
        for (int i = 0; i < THREADS / 32; i++) tot += ws[i];
        const float rinv = rsqrtf(tot * (1.0f / CDIM) + EPSF);

        // t[e] = agg * w;  th[i] = hpost[i] * rinv
        float t[8];
        #pragma unroll
        for (int e = 0; e < 8; e++) t[e] = agg[e] * wa[e];

        // ---- Mix + streaming stores ----
        float4* __restrict__ orow =
            reinterpret_cast<float4*>(out) + (size_t)r * (NS * C4);
        #pragma unroll
        for (int i = 0; i < NS; i++) {
            const float h = hpost[i] * rinv;
            float o[8];
            #pragma unroll
            for (int e = 0; e < 8; e++) {
                o[e] = P[i][0] * va[0][e] + P[i][1] * va[1][e]
                     + P[i][2] * va[2][e] + P[i][3] * va[3][e]
                     + h * t[e];
            }
            __stcs(&orow[i * C4 + tid],
                   make_float4(o[0], o[1], o[2], o[3]));
            __stcs(&orow[i * C4 + tid + THREADS],
                   make_float4(o[4], o[5], o[6], o[7]));
        }
    }
}

extern "C" void kernel_launch(void* const* d_in, const int* in_sizes, int n_in,
                              void* d_out, int out_size)
{
    const float* x      = (const float*)d_in[0];
    const float* w      = (const float*)d_in[1];
    const float* H_pre  = (const float*)d_in[2];
    const float* H_post = (const float*)d_in[3];
    const float* H_res  = (const float*)d_in[4];
    float* out          = (float*)d_out;

    const int B = in_sizes[0] / (NS * CDIM);

    int dev = 0, nsm = 148;
    cudaGetDevice(&dev);
    cudaDeviceGetAttribute(&nsm, cudaDevAttrMultiProcessorCount, dev);

    cudaFuncSetAttribute(mhc_cpasync_kernel,
                         cudaFuncAttributeMaxDynamicSharedMemorySize,
                         SMEM_BYTES);

    mhc_cpasync_kernel<<<nsm, THREADS, SMEM_BYTES>>>(
        x, w, H_pre, H_post, H_res, out, B);
}